// round 14
// baseline (speedup 1.0000x reference)
#include <cuda_runtime.h>
#include <cuda_fp16.h>
#include <math.h>

#define NN   50000
#define EE   200000
#define BB   2048
#define ATT  16
#define ETT  4
#define H    32
#define LL   3
#define LAT  64
#define HLD  256
#define FEAT 245
#define FEATP 248
#define MAXN 50.0f
#define GPB  8
#define PIT  40       // smem half pitch (conflict-free fragment loads)
#define NBLK 148      // persistent blocks (one wave, co-resident)
#define NTHR 1024
#define NTILE 391     // ceil(NN/128)

typedef unsigned int u32;

// ---------------- scratch (device globals; no allocation allowed) ----------------
__device__ float  g_h[NN * H];           // current (normalized) node features
__device__ float  g_hnew[NN * H];        // pre-BN features (relu(nx)+h)
__device__ __half g_Ph[NN * 5 * H];      // fp16: per-node h@W_t (t=0..3) and h@Bmat (t=4)
__device__ float  g_hr[NN * H];          // per-node h@root_w (fp32)
__device__ float  g_agg[NN * H];
__device__ float  g_deg[NN];
__device__ float  g_invdeg[NN];
__device__ float  g_cnt[BB];
__device__ float  g_feats[BB * FEAT];    // only cols [0,53) used directly
__device__ float  g_poolsum[LL * BB * H];
__device__ float  g_poolmax[LL * BB * H];
__device__ float  g_bnsum[H];
__device__ float  g_bnsq[H];
__device__ __half g_WT[LL * 6 * H * H];  // pre-transposed fp16 weights [l][m][col][hh]
__device__ unsigned g_cntbar = 0;        // software grid barrier
__device__ unsigned g_gen = 0;

// float atomic max via monotone int/uint mapping
__device__ __forceinline__ void atomicMaxFloat(float* addr, float v) {
    if (v >= 0.f) atomicMax((int*)addr, __float_as_int(v));
    else          atomicMin((unsigned int*)addr, __float_as_uint(v));
}

// vector reduction: one instruction, 16B per lane
__device__ __forceinline__ void redAddF4(float* addr, float4 v) {
    asm volatile("red.global.add.v4.f32 [%0], {%1, %2, %3, %4};"
                 :: "l"(addr), "f"(v.x), "f"(v.y), "f"(v.z), "f"(v.w) : "memory");
}

// load 4 consecutive halves (8B) and widen to float4
__device__ __forceinline__ float4 ldP4h(const __half* p) {
    uint2 u = *(const uint2*)p;
    __half2 a = *reinterpret_cast<__half2*>(&u.x);
    __half2 b = *reinterpret_cast<__half2*>(&u.y);
    float2 fa = __half22float2(a), fb = __half22float2(b);
    return make_float4(fa.x, fa.y, fb.x, fb.y);
}

// mma.sync m16n8k16 fp16 in / fp32 accumulate
__device__ __forceinline__ void mma16816(float& c0, float& c1, float& c2, float& c3,
                                         u32 a0, u32 a1, u32 a2, u32 a3, u32 b0, u32 b1) {
    asm volatile(
        "mma.sync.aligned.m16n8k16.row.col.f32.f16.f16.f32 "
        "{%0,%1,%2,%3}, {%4,%5,%6,%7}, {%8,%9}, {%0,%1,%2,%3};"
        : "+f"(c0), "+f"(c1), "+f"(c2), "+f"(c3)
        : "r"(a0), "r"(a1), "r"(a2), "r"(a3), "r"(b0), "r"(b1));
}

// software grid barrier (all NBLK blocks co-resident; CG-fallback pattern)
__device__ __forceinline__ void gsync() {
    __syncthreads();
    if (threadIdx.x == 0) {
        __threadfence();
        unsigned my = atomicAdd(&g_gen, 0u);
        if (atomicAdd(&g_cntbar, 1u) == (unsigned)(gridDim.x - 1)) {
            atomicExch(&g_cntbar, 0u);
            atomicAdd(&g_gen, 1u);
        } else {
            while (atomicAdd(&g_gen, 0u) == my) __nanosleep(64);
        }
        __threadfence();
    }
    __syncthreads();
}

// ---------------- one-time zero (float4) ----------------
__global__ void k_zero() {
    int i = blockIdx.x * blockDim.x + threadIdx.x;
    const float4 z4 = make_float4(0.f, 0.f, 0.f, 0.f);
    const float4 ninf4 = make_float4(-INFINITY, -INFINITY, -INFINITY, -INFINITY);
    if (i < NN * H / 4)      ((float4*)g_agg)[i] = z4;
    if (i < BB * FEAT / 4)   ((float4*)g_feats)[i] = z4;
    if (i < NN / 4)          ((float4*)g_deg)[i] = z4;
    if (i < BB / 4)          ((float4*)g_cnt)[i] = z4;
    if (i < LL * BB * H / 4) { ((float4*)g_poolsum)[i] = z4; ((float4*)g_poolmax)[i] = ninf4; }
    if (i < H)               { g_bnsum[i] = 0.f; g_bnsq[i] = 0.f; }
}

// ---------------- fused: edge stats + x pools (run-length) + weight pre-transform ----------------
__global__ void k_stats(const int* __restrict__ ei, const float* __restrict__ et,
                        const float* __restrict__ x, const int* __restrict__ batch,
                        const float* __restrict__ enw, const float* __restrict__ enb,
                        const float* __restrict__ rw) {
    int i = blockIdx.x * blockDim.x + threadIdx.x;
    if (i < LL * 6 * H * H) {
        int l = i / 6144, rd = i % 6144;
        int m = rd >> 10, rest = rd & 1023;
        int col = rest >> 5, hh = rest & 31;     // dest layout [m][col][hh]
        float w;
        if (m < 4)       w = enw[(l * ETT + m) * H * H + hh * H + col];
        else if (m == 4) w = enb[l * H * H + hh * H + col];
        else             w = rw[l * H * H + hh * H + col];
        g_WT[i] = __float2half(w);
    }
    if (i < (NN / 8) * 16) {
        int c = i & 15;
        int base = (i >> 4) * 8;
        int gcur = -1;
        float s = 0.f, mx = 0.f, cnt = 0.f;
#pragma unroll
        for (int j = 0; j < 8; j++) {
            int n = base + j;
            if (n >= NN) break;
            int g = batch[n];
            float v = x[n * ATT + c];
            if (g != gcur) {
                if (gcur >= 0) {
                    atomicAdd(&g_feats[gcur * FEAT + 21 + c], s);
                    atomicMaxFloat(&g_feats[gcur * FEAT + 37 + c], mx);
                    if (c == 0) atomicAdd(&g_cnt[gcur], cnt);
                }
                gcur = g; s = v; mx = v; cnt = 1.f;
            } else { s += v; mx = fmaxf(mx, v); cnt += 1.f; }
        }
        if (gcur >= 0) {
            atomicAdd(&g_feats[gcur * FEAT + 21 + c], s);
            atomicMaxFloat(&g_feats[gcur * FEAT + 37 + c], mx);
            if (c == 0) atomicAdd(&g_cnt[gcur], cnt);
        }
    }
    if (i < EE) {
        int s = ei[i];
        int t = ei[EE + i];
        atomicAdd(&g_deg[t], 1.f);
        int g = batch[s];
        const float inv = 1.f / MAXN;
#pragma unroll
        for (int j = 0; j < ETT; j++)
            atomicAdd(&g_feats[g * FEAT + 1 + j], et[i * ETT + j] * inv);
    }
}

// ---------------- initial node MLP (thread per node) + invdeg / x-feature finish ----------------
__global__ void k_init_mlp(const float* __restrict__ x,
                           const float* __restrict__ w0, const float* __restrict__ b0,
                           const float* __restrict__ w1, const float* __restrict__ b1) {
    __shared__ float sw0[ATT * H], sw1[H * H], sb0[H], sb1[H];
    int tid = threadIdx.x;
    for (int i = tid; i < ATT * H; i += blockDim.x) sw0[i] = w0[i];
    for (int i = tid; i < H * H;  i += blockDim.x) sw1[i] = w1[i];
    if (tid < H) { sb0[tid] = b0[tid]; sb1[tid] = b1[tid]; }
    __syncthreads();

    int gid = blockIdx.x * blockDim.x + tid;
    if (gid < NN) g_invdeg[gid] = 1.f / fmaxf(g_deg[gid], 1.f);
    if (gid < BB * ATT) {
        int g = gid / ATT, c = gid % ATT;
        float cnt = g_cnt[g];
        float sum = g_feats[g * FEAT + 21 + c];
        g_feats[g * FEAT + 5 + c]  = sum / MAXN;
        g_feats[g * FEAT + 21 + c] = sum / fmaxf(cnt, 1.f);
        if (cnt <= 0.f) g_feats[g * FEAT + 37 + c] = 0.f;
        if (c == 0) g_feats[g * FEAT] = cnt / MAXN;
    }

    int n = gid;
    if (n >= NN) return;
    float xr[ATT];
#pragma unroll
    for (int q = 0; q < ATT / 4; q++) {
        float4 v = *(const float4*)&x[n * ATT + q * 4];
        xr[q * 4 + 0] = v.x; xr[q * 4 + 1] = v.y; xr[q * 4 + 2] = v.z; xr[q * 4 + 3] = v.w;
    }
    float t[H];
#pragma unroll
    for (int o = 0; o < H / 4; o++) {
        float4 bv = *(const float4*)&sb0[o * 4];
        t[o * 4 + 0] = bv.x; t[o * 4 + 1] = bv.y; t[o * 4 + 2] = bv.z; t[o * 4 + 3] = bv.w;
    }
#pragma unroll
    for (int a = 0; a < ATT; a++) {
        float xa = xr[a];
#pragma unroll
        for (int o = 0; o < H / 4; o++) {
            float4 w = *(const float4*)&sw0[a * H + o * 4];
            t[o * 4 + 0] = fmaf(xa, w.x, t[o * 4 + 0]);
            t[o * 4 + 1] = fmaf(xa, w.y, t[o * 4 + 1]);
            t[o * 4 + 2] = fmaf(xa, w.z, t[o * 4 + 2]);
            t[o * 4 + 3] = fmaf(xa, w.w, t[o * 4 + 3]);
        }
    }
    float hv[H];
#pragma unroll
    for (int o = 0; o < H / 4; o++) {
        float4 bv = *(const float4*)&sb1[o * 4];
        hv[o * 4 + 0] = bv.x; hv[o * 4 + 1] = bv.y; hv[o * 4 + 2] = bv.z; hv[o * 4 + 3] = bv.w;
    }
#pragma unroll
    for (int k = 0; k < H; k++) {
        float tk = fmaxf(t[k], 0.f);
#pragma unroll
        for (int o = 0; o < H / 4; o++) {
            float4 w = *(const float4*)&sw1[k * H + o * 4];
            hv[o * 4 + 0] = fmaf(tk, w.x, hv[o * 4 + 0]);
            hv[o * 4 + 1] = fmaf(tk, w.y, hv[o * 4 + 1]);
            hv[o * 4 + 2] = fmaf(tk, w.z, hv[o * 4 + 2]);
            hv[o * 4 + 3] = fmaf(tk, w.w, hv[o * 4 + 3]);
        }
    }
#pragma unroll
    for (int o = 0; o < H / 4; o++)
        *(float4*)&g_h[n * H + o * 4] = make_float4(hv[o*4], hv[o*4+1], hv[o*4+2], hv[o*4+3]);
}

// ---------------- persistent 3-layer kernel: precompute → edge → update per layer,
//                  software grid barriers between phases. 148 blocks × 1024 threads. ----------------
__global__ void __launch_bounds__(NTHR, 1)
k_layers(const int* __restrict__ ei, const float* __restrict__ et,
         const int* __restrict__ batch, const float* __restrict__ cb,
         const float* __restrict__ gamma, const float* __restrict__ beta) {
    __shared__ __half sWT[192 * PIT];   // 15 KB
    __shared__ __half sH[128 * PIT];    // 10 KB
    __shared__ float  sA[H], sB[H];
    __shared__ float  ssum[H], ssq[H];

    int tid = threadIdx.x;
    int bid = blockIdx.x;
    int flat = bid * NTHR + tid;

    for (int l = 0; l < LL; l++) {
        // ===== phase P: precompute GEMM (tensor cores) =====
        if (tid < H) {
            if (l > 0) {
                float mu  = g_bnsum[tid] / (float)NN;
                float var = g_bnsq[tid] / (float)NN - mu * mu;
                float A = gamma[(l - 1) * H + tid] * rsqrtf(var + 1e-5f);
                sA[tid] = A;
                sB[tid] = beta[(l - 1) * H + tid] - mu * A;
            } else { sA[tid] = 1.f; sB[tid] = 0.f; }
        }
        {   // weight copy: once per block per layer
            const __half* wsrc = &g_WT[l * 6144];
            for (int i = tid; i < 1536; i += NTHR) {
                int e4 = i * 4;
                int cg = e4 >> 5;
                int h0 = e4 & 31;
                *reinterpret_cast<uint2*>(&sWT[cg * PIT + h0]) =
                    *reinterpret_cast<const uint2*>(&wsrc[e4]);
            }
        }
        __syncthreads();

        for (int tile = bid; tile < NTILE; tile += NBLK) {
            int nb0 = tile * 128;
            // stage h as fp16 (1024 threads = 128 rows × 8 quads, one item each)
            {
                int r = tid >> 3, q4 = tid & 7;
                int n = nb0 + r;
                float4 v = make_float4(0.f, 0.f, 0.f, 0.f);
                if (n < NN) {
                    if (l == 0) v = *(const float4*)&g_h[n * H + q4 * 4];
                    else {
                        float4 hn = *(const float4*)&g_hnew[n * H + q4 * 4];
                        float4 Av = *(const float4*)&sA[q4 * 4];
                        float4 Bv = *(const float4*)&sB[q4 * 4];
                        v.x = fmaf(hn.x, Av.x, Bv.x);
                        v.y = fmaf(hn.y, Av.y, Bv.y);
                        v.z = fmaf(hn.z, Av.z, Bv.z);
                        v.w = fmaf(hn.w, Av.w, Bv.w);
                        *(float4*)&g_h[n * H + q4 * 4] = v;
                    }
                }
                __half2 p0 = __floats2half2_rn(v.x, v.y);
                __half2 p1 = __floats2half2_rn(v.z, v.w);
                uint2 pk;
                pk.x = *reinterpret_cast<u32*>(&p0);
                pk.y = *reinterpret_cast<u32*>(&p1);
                *reinterpret_cast<uint2*>(&sH[r * PIT + q4 * 4]) = pk;
            }
            __syncthreads();

            // mma: warps 0-7 (tid < 256), one 16-row M-tile each (16 | NN → warp-level guard OK)
            if (tid < 256) {
                int wib = tid >> 5;
                int lane = tid & 31;
                int g = lane >> 2;
                int q = lane & 3;
                int nb = nb0 + wib * 16;
                if (nb < NN) {
                    int r0 = wib * 16 + g;
                    u32 a[2][4];
#pragma unroll
                    for (int kk = 0; kk < 2; kk++) {
                        int cbk = 2 * q + 16 * kk;
                        a[kk][0] = *reinterpret_cast<const u32*>(&sH[(r0)     * PIT + cbk]);
                        a[kk][1] = *reinterpret_cast<const u32*>(&sH[(r0 + 8) * PIT + cbk]);
                        a[kk][2] = *reinterpret_cast<const u32*>(&sH[(r0)     * PIT + cbk + 8]);
                        a[kk][3] = *reinterpret_cast<const u32*>(&sH[(r0 + 8) * PIT + cbk + 8]);
                    }
                    int n1 = nb + g;
                    int n2 = n1 + 8;
#pragma unroll
                    for (int m = 0; m < 6; m++) {
#pragma unroll
                        for (int jt = 0; jt < 4; jt++) {
                            const __half* wrow = &sWT[(m * 32 + jt * 8 + g) * PIT];
                            u32 b0a = *reinterpret_cast<const u32*>(&wrow[2 * q]);
                            u32 b1a = *reinterpret_cast<const u32*>(&wrow[2 * q + 8]);
                            u32 b0b = *reinterpret_cast<const u32*>(&wrow[2 * q + 16]);
                            u32 b1b = *reinterpret_cast<const u32*>(&wrow[2 * q + 24]);
                            float c0 = 0.f, c1 = 0.f, c2 = 0.f, c3 = 0.f;
                            mma16816(c0, c1, c2, c3, a[0][0], a[0][1], a[0][2], a[0][3], b0a, b1a);
                            mma16816(c0, c1, c2, c3, a[1][0], a[1][1], a[1][2], a[1][3], b0b, b1b);
                            int colb = jt * 8 + 2 * q;
                            if (m < 5) {
                                *reinterpret_cast<__half2*>(&g_Ph[n1 * 5 * H + m * H + colb]) =
                                    __floats2half2_rn(c0, c1);
                                *reinterpret_cast<__half2*>(&g_Ph[n2 * 5 * H + m * H + colb]) =
                                    __floats2half2_rn(c2, c3);
                            } else {
                                *reinterpret_cast<float2*>(&g_hr[n1 * H + colb]) = make_float2(c0, c1);
                                *reinterpret_cast<float2*>(&g_hr[n2 * H + colb]) = make_float2(c2, c3);
                            }
                        }
                    }
                }
            }
            __syncthreads();   // protect sH before next tile overwrites
        }
        gsync();

        // ===== phase E: edge scatter (octet per edge) + BN-sum reset =====
        if (flat < H)          g_bnsum[flat] = 0.f;
        else if (flat < 2 * H) g_bnsq[flat - H] = 0.f;
        for (int i = flat; i < EE * 8; i += NBLK * NTHR) {
            int e = i >> 3;
            int q = i & 7;
            int s = ei[e];
            int t = ei[EE + e];
            float4 ev = *(const float4*)&et[e * ETT];
            const __half* __restrict__ Pr = &g_Ph[s * 5 * H];
            float4 p0 = ldP4h(&Pr[0 * H + q * 4]);
            float4 p1 = ldP4h(&Pr[1 * H + q * 4]);
            float4 p2 = ldP4h(&Pr[2 * H + q * 4]);
            float4 p3 = ldP4h(&Pr[3 * H + q * 4]);
            float4 p4 = ldP4h(&Pr[4 * H + q * 4]);
            float4 acc;
            acc.x = fmaf(ev.x, p0.x, fmaf(ev.y, p1.x, fmaf(ev.z, p2.x, fmaf(ev.w, p3.x, p4.x))));
            acc.y = fmaf(ev.x, p0.y, fmaf(ev.y, p1.y, fmaf(ev.z, p2.y, fmaf(ev.w, p3.y, p4.y))));
            acc.z = fmaf(ev.x, p0.z, fmaf(ev.y, p1.z, fmaf(ev.z, p2.z, fmaf(ev.w, p3.z, p4.z))));
            acc.w = fmaf(ev.x, p0.w, fmaf(ev.y, p1.w, fmaf(ev.z, p2.w, fmaf(ev.w, p3.w, p4.w))));
            redAddF4(&g_agg[t * H + q * 4], acc);
        }
        gsync();

        // ===== phase U: node update (warp per 8-node span, run-length pools) =====
        {
            int lane = tid & 31;
            if (tid < H) { ssum[tid] = 0.f; ssq[tid] = 0.f; }
            __syncthreads();
            float bias = cb[l * H + lane];
            float lsum = 0.f, lsq = 0.f;
            float* psum = &g_poolsum[l * BB * H];
            float* pmax = &g_poolmax[l * BB * H];
            int gw = bid * (NTHR / 32) + (tid >> 5);
            for (int span = gw; span < (NN + 7) / 8; span += NBLK * (NTHR / 32)) {
                int base = span * 8;
                int gcur = -1;
                float ps = 0.f, pm = 0.f;
#pragma unroll
                for (int j = 0; j < 8; j++) {
                    int n = base + j;
                    if (n >= NN) break;
                    int i = n * H + lane;
                    float hv = g_h[i];
                    float nx = bias + g_agg[i] * g_invdeg[n] + g_hr[i];
                    g_agg[i] = 0.f;
                    int g = batch[n];
                    float hp = fmaxf(nx, 0.f) + hv;
                    g_hnew[i] = hp;
                    lsum += hp; lsq += hp * hp;
                    if (g != gcur) {
                        if (gcur >= 0) {
                            atomicAdd(&psum[gcur * H + lane], ps);
                            atomicMaxFloat(&pmax[gcur * H + lane], pm);
                        }
                        gcur = g; ps = nx; pm = nx;
                    } else {
                        ps += nx; pm = fmaxf(pm, nx);
                    }
                }
                if (gcur >= 0) {
                    atomicAdd(&psum[gcur * H + lane], ps);
                    atomicMaxFloat(&pmax[gcur * H + lane], pm);
                }
            }
            atomicAdd(&ssum[lane], lsum);
            atomicAdd(&ssq[lane], lsq);
            __syncthreads();
            if (tid < H) {
                atomicAdd(&g_bnsum[tid], ssum[tid]);
                atomicAdd(&g_bnsq[tid], ssq[tid]);
            }
        }
        gsync();
    }
}

// ---------------- final MLP: pool-finish fused into the feature load ----------------
__global__ void k_final(const float* __restrict__ w0, const float* __restrict__ b0,
                        const float* __restrict__ w1, const float* __restrict__ b1,
                        float* __restrict__ out) {
    __shared__ float sf[GPB * FEATP];
    __shared__ float st[GPB * HLD];
    int tid = threadIdx.x;
    int g0 = blockIdx.x * GPB;
    for (int i = tid; i < GPB * FEATP; i += blockDim.x) {
        int gg = i / FEATP, r = i - gg * FEATP;
        int g = g0 + gg;
        float v = 0.f;
        if (r < 53) {
            v = g_feats[g * FEAT + r];
        } else if (r < FEAT) {
            int rr = r - 53;
            int l = rr >> 6, k = rr & 63;
            float cnt = g_cnt[g];
            if (k < 32) v = g_poolsum[l * BB * H + g * H + k] / fmaxf(cnt, 1.f);
            else        v = (cnt > 0.f) ? g_poolmax[l * BB * H + g * H + (k - 32)] : 0.f;
        }
        sf[i] = v;
    }
    __syncthreads();
    {
        float acc[GPB];
        float bb = b0[tid];
#pragma unroll
        for (int gg = 0; gg < GPB; gg++) acc[gg] = bb;
        for (int i = 0; i < 244; i += 4) {
            float wa = w0[(i + 0) * HLD + tid];
            float wb = w0[(i + 1) * HLD + tid];
            float wc = w0[(i + 2) * HLD + tid];
            float wd = w0[(i + 3) * HLD + tid];
#pragma unroll
            for (int gg = 0; gg < GPB; gg++) {
                float4 f = *(const float4*)&sf[gg * FEATP + i];
                acc[gg] = fmaf(f.x, wa, acc[gg]);
                acc[gg] = fmaf(f.y, wb, acc[gg]);
                acc[gg] = fmaf(f.z, wc, acc[gg]);
                acc[gg] = fmaf(f.w, wd, acc[gg]);
            }
        }
        float wl = w0[244 * HLD + tid];
#pragma unroll
        for (int gg = 0; gg < GPB; gg++) acc[gg] = fmaf(sf[gg * FEATP + 244], wl, acc[gg]);
#pragma unroll
        for (int gg = 0; gg < GPB; gg++) st[gg * HLD + tid] = fmaxf(acc[gg], 0.f);
    }
    __syncthreads();
    {
        int col = tid & 127;
        int gbase = (tid >> 7) * 4;
        float bb = b1[col];
        float acc[4];
#pragma unroll
        for (int q = 0; q < 4; q++) acc[q] = bb;
        for (int i = 0; i < HLD; i += 4) {
            float wa = w1[(i + 0) * 2 * LAT + col];
            float wb = w1[(i + 1) * 2 * LAT + col];
            float wc = w1[(i + 2) * 2 * LAT + col];
            float wd = w1[(i + 3) * 2 * LAT + col];
#pragma unroll
            for (int q = 0; q < 4; q++) {
                float4 s4 = *(const float4*)&st[(gbase + q) * HLD + i];
                acc[q] = fmaf(s4.x, wa, acc[q]);
                acc[q] = fmaf(s4.y, wb, acc[q]);
                acc[q] = fmaf(s4.z, wc, acc[q]);
                acc[q] = fmaf(s4.w, wd, acc[q]);
            }
        }
#pragma unroll
        for (int q = 0; q < 4; q++) {
            int g = g0 + gbase + q;
            if (col < LAT) out[g * LAT + col] = acc[q];
            else           out[BB * LAT + g * LAT + (col - LAT)] = acc[q];
        }
    }
}

// ---------------- launch ----------------
extern "C" void kernel_launch(void* const* d_in, const int* in_sizes, int n_in,
                              void* d_out, int out_size) {
    const float* x      = (const float*)d_in[0];
    const int*   ei     = (const int*)  d_in[1];
    const float* et     = (const float*)d_in[2];
    const int*   batch  = (const int*)  d_in[3];
    const float* mlp0_w = (const float*)d_in[4];
    const float* mlp0_b = (const float*)d_in[5];
    const float* mlp1_w = (const float*)d_in[6];
    const float* mlp1_b = (const float*)d_in[7];
    const float* enw    = (const float*)d_in[8];
    const float* enb    = (const float*)d_in[9];
    const float* rw     = (const float*)d_in[10];
    const float* cb     = (const float*)d_in[11];
    const float* gamma  = (const float*)d_in[12];
    const float* beta   = (const float*)d_in[13];
    const float* f0w    = (const float*)d_in[14];
    const float* f0b    = (const float*)d_in[15];
    const float* f1w    = (const float*)d_in[16];
    const float* f1b    = (const float*)d_in[17];
    float* out = (float*)d_out;

    k_zero<<<(NN * H / 4 + 255) / 256, 256>>>();
    k_stats<<<(EE + 255) / 256, 256>>>(ei, et, x, batch, enw, enb, rw);
    k_init_mlp<<<(NN + 255) / 256, 256>>>(x, mlp0_w, mlp0_b, mlp1_w, mlp1_b);
    k_layers<<<NBLK, NTHR>>>(ei, et, batch, cb, gamma, beta);
    k_final<<<BB / GPB, 256>>>(f0w, f0b, f1w, f1b, out);
}

// round 15
// speedup vs baseline: 1.0981x; 1.0981x over previous
#include <cuda_runtime.h>
#include <cuda_fp16.h>
#include <math.h>

#define NN   50000
#define EE   200000
#define BB   2048
#define ATT  16
#define ETT  4
#define H    32
#define LL   3
#define LAT  64
#define HLD  256
#define FEAT 245
#define FEATP 248
#define MAXN 50.0f
#define GPB  8
#define PIT  40     // smem half pitch (conflict-free fragment loads; 80B rows, 16B-aligned)

typedef unsigned int u32;

// ---------------- scratch (device globals; no allocation allowed) ----------------
__device__ float  g_h[NN * H];           // current (normalized) node features
__device__ float  g_hnew[NN * H];        // pre-BN features (relu(nx)+h)
__device__ __half g_Ph[NN * 5 * H];      // fp16: per-node h@W_t (t=0..3) and h@Bmat (t=4)
__device__ float  g_hr[NN * H];          // per-node h@root_w (fp32)
__device__ float  g_agg[NN * H];
__device__ float  g_deg[NN];
__device__ float  g_invdeg[NN];
__device__ float  g_cnt[BB];
__device__ float  g_feats[BB * FEAT];    // only cols [0,53) used directly
__device__ float  g_poolsum[LL * BB * H];
__device__ float  g_poolmax[LL * BB * H];
__device__ float  g_bnsum[H];
__device__ float  g_bnsq[H];
__device__ __half g_WT[LL * 6 * H * H];  // pre-transposed fp16 weights [l][m][col][hh]

// float atomic max via monotone int/uint mapping
__device__ __forceinline__ void atomicMaxFloat(float* addr, float v) {
    if (v >= 0.f) atomicMax((int*)addr, __float_as_int(v));
    else          atomicMin((unsigned int*)addr, __float_as_uint(v));
}

// vector reduction: one instruction, 16B per lane
__device__ __forceinline__ void redAddF4(float* addr, float4 v) {
    asm volatile("red.global.add.v4.f32 [%0], {%1, %2, %3, %4};"
                 :: "l"(addr), "f"(v.x), "f"(v.y), "f"(v.z), "f"(v.w) : "memory");
}

// load 4 consecutive halves (8B) and widen to float4
__device__ __forceinline__ float4 ldP4h(const __half* p) {
    uint2 u = *(const uint2*)p;
    __half2 a = *reinterpret_cast<__half2*>(&u.x);
    __half2 b = *reinterpret_cast<__half2*>(&u.y);
    float2 fa = __half22float2(a), fb = __half22float2(b);
    return make_float4(fa.x, fa.y, fb.x, fb.y);
}

// mma.sync m16n8k16 fp16 in / fp32 accumulate
__device__ __forceinline__ void mma16816(float& c0, float& c1, float& c2, float& c3,
                                         u32 a0, u32 a1, u32 a2, u32 a3, u32 b0, u32 b1) {
    asm volatile(
        "mma.sync.aligned.m16n8k16.row.col.f32.f16.f16.f32 "
        "{%0,%1,%2,%3}, {%4,%5,%6,%7}, {%8,%9}, {%0,%1,%2,%3};"
        : "+f"(c0), "+f"(c1), "+f"(c2), "+f"(c3)
        : "r"(a0), "r"(a1), "r"(a2), "r"(a3), "r"(b0), "r"(b1));
}

// ---------------- one-time zero (float4) ----------------
__global__ void k_zero() {
    int i = blockIdx.x * blockDim.x + threadIdx.x;
    const float4 z4 = make_float4(0.f, 0.f, 0.f, 0.f);
    const float4 ninf4 = make_float4(-INFINITY, -INFINITY, -INFINITY, -INFINITY);
    if (i < NN * H / 4)      ((float4*)g_agg)[i] = z4;
    if (i < BB * FEAT / 4)   ((float4*)g_feats)[i] = z4;
    if (i < NN / 4)          ((float4*)g_deg)[i] = z4;
    if (i < BB / 4)          ((float4*)g_cnt)[i] = z4;
    if (i < LL * BB * H / 4) { ((float4*)g_poolsum)[i] = z4; ((float4*)g_poolmax)[i] = ninf4; }
    if (i < H)               { g_bnsum[i] = 0.f; g_bnsq[i] = 0.f; }
}

// ---------------- fused: edge stats + x pools (run-length) + weight pre-transform ----------------
__global__ void k_stats(const int* __restrict__ ei, const float* __restrict__ et,
                        const float* __restrict__ x, const int* __restrict__ batch,
                        const float* __restrict__ enw, const float* __restrict__ enb,
                        const float* __restrict__ rw) {
    int i = blockIdx.x * blockDim.x + threadIdx.x;
    if (i < LL * 6 * H * H) {
        int l = i / 6144, rd = i % 6144;
        int m = rd >> 10, rest = rd & 1023;
        int col = rest >> 5, hh = rest & 31;     // dest layout [m][col][hh]
        float w;
        if (m < 4)       w = enw[(l * ETT + m) * H * H + hh * H + col];
        else if (m == 4) w = enb[l * H * H + hh * H + col];
        else             w = rw[l * H * H + hh * H + col];
        g_WT[i] = __float2half(w);
    }
    if (i < (NN / 8) * 16) {
        int c = i & 15;
        int base = (i >> 4) * 8;
        int gcur = -1;
        float s = 0.f, mx = 0.f, cnt = 0.f;
#pragma unroll
        for (int j = 0; j < 8; j++) {
            int n = base + j;
            if (n >= NN) break;
            int g = batch[n];
            float v = x[n * ATT + c];
            if (g != gcur) {
                if (gcur >= 0) {
                    atomicAdd(&g_feats[gcur * FEAT + 21 + c], s);
                    atomicMaxFloat(&g_feats[gcur * FEAT + 37 + c], mx);
                    if (c == 0) atomicAdd(&g_cnt[gcur], cnt);
                }
                gcur = g; s = v; mx = v; cnt = 1.f;
            } else { s += v; mx = fmaxf(mx, v); cnt += 1.f; }
        }
        if (gcur >= 0) {
            atomicAdd(&g_feats[gcur * FEAT + 21 + c], s);
            atomicMaxFloat(&g_feats[gcur * FEAT + 37 + c], mx);
            if (c == 0) atomicAdd(&g_cnt[gcur], cnt);
        }
    }
    if (i < EE) {
        int s = ei[i];
        int t = ei[EE + i];
        atomicAdd(&g_deg[t], 1.f);
        int g = batch[s];
        const float inv = 1.f / MAXN;
#pragma unroll
        for (int j = 0; j < ETT; j++)
            atomicAdd(&g_feats[g * FEAT + 1 + j], et[i * ETT + j] * inv);
    }
}

// ---------------- initial node MLP (thread per node) + invdeg / x-feature finish ----------------
__global__ void k_init_mlp(const float* __restrict__ x,
                           const float* __restrict__ w0, const float* __restrict__ b0,
                           const float* __restrict__ w1, const float* __restrict__ b1) {
    __shared__ float sw0[ATT * H], sw1[H * H], sb0[H], sb1[H];
    int tid = threadIdx.x;
    for (int i = tid; i < ATT * H; i += blockDim.x) sw0[i] = w0[i];
    for (int i = tid; i < H * H;  i += blockDim.x) sw1[i] = w1[i];
    if (tid < H) { sb0[tid] = b0[tid]; sb1[tid] = b1[tid]; }
    __syncthreads();

    int gid = blockIdx.x * blockDim.x + tid;
    if (gid < NN) g_invdeg[gid] = 1.f / fmaxf(g_deg[gid], 1.f);
    if (gid < BB * ATT) {
        int g = gid / ATT, c = gid % ATT;
        float cnt = g_cnt[g];
        float sum = g_feats[g * FEAT + 21 + c];
        g_feats[g * FEAT + 5 + c]  = sum / MAXN;
        g_feats[g * FEAT + 21 + c] = sum / fmaxf(cnt, 1.f);
        if (cnt <= 0.f) g_feats[g * FEAT + 37 + c] = 0.f;
        if (c == 0) g_feats[g * FEAT] = cnt / MAXN;
    }

    int n = gid;
    if (n >= NN) return;
    float xr[ATT];
#pragma unroll
    for (int q = 0; q < ATT / 4; q++) {
        float4 v = *(const float4*)&x[n * ATT + q * 4];
        xr[q * 4 + 0] = v.x; xr[q * 4 + 1] = v.y; xr[q * 4 + 2] = v.z; xr[q * 4 + 3] = v.w;
    }
    float t[H];
#pragma unroll
    for (int o = 0; o < H / 4; o++) {
        float4 bv = *(const float4*)&sb0[o * 4];
        t[o * 4 + 0] = bv.x; t[o * 4 + 1] = bv.y; t[o * 4 + 2] = bv.z; t[o * 4 + 3] = bv.w;
    }
#pragma unroll
    for (int a = 0; a < ATT; a++) {
        float xa = xr[a];
#pragma unroll
        for (int o = 0; o < H / 4; o++) {
            float4 w = *(const float4*)&sw0[a * H + o * 4];
            t[o * 4 + 0] = fmaf(xa, w.x, t[o * 4 + 0]);
            t[o * 4 + 1] = fmaf(xa, w.y, t[o * 4 + 1]);
            t[o * 4 + 2] = fmaf(xa, w.z, t[o * 4 + 2]);
            t[o * 4 + 3] = fmaf(xa, w.w, t[o * 4 + 3]);
        }
    }
    float hv[H];
#pragma unroll
    for (int o = 0; o < H / 4; o++) {
        float4 bv = *(const float4*)&sb1[o * 4];
        hv[o * 4 + 0] = bv.x; hv[o * 4 + 1] = bv.y; hv[o * 4 + 2] = bv.z; hv[o * 4 + 3] = bv.w;
    }
#pragma unroll
    for (int k = 0; k < H; k++) {
        float tk = fmaxf(t[k], 0.f);
#pragma unroll
        for (int o = 0; o < H / 4; o++) {
            float4 w = *(const float4*)&sw1[k * H + o * 4];
            hv[o * 4 + 0] = fmaf(tk, w.x, hv[o * 4 + 0]);
            hv[o * 4 + 1] = fmaf(tk, w.y, hv[o * 4 + 1]);
            hv[o * 4 + 2] = fmaf(tk, w.z, hv[o * 4 + 2]);
            hv[o * 4 + 3] = fmaf(tk, w.w, hv[o * 4 + 3]);
        }
    }
#pragma unroll
    for (int o = 0; o < H / 4; o++)
        *(float4*)&g_h[n * H + o * 4] = make_float4(hv[o*4], hv[o*4+1], hv[o*4+2], hv[o*4+3]);
}

// ---------------- precompute GEMM on tensor cores (256 thr / 128 nodes, grid 391).
//                  Ph stores staged through smem (reusing sH) → coalesced uint4 global
//                  stores. hr (fp32) stays direct. Fuses prev-layer BN-finish. ----------------
__global__ void k_precompute(const float* __restrict__ gamma, const float* __restrict__ beta,
                             int l) {
    __shared__ __half sWT[192 * PIT];   // 15 KB
    __shared__ __half sH[128 * PIT];    // 10 KB: h staging, then Ph epilogue buffer
    __shared__ float  sA[H], sB[H];
    int tid = threadIdx.x;

    if (tid < H) {
        if (l > 0) {
            float mu  = g_bnsum[tid] / (float)NN;
            float var = g_bnsq[tid] / (float)NN - mu * mu;
            float A = gamma[(l - 1) * H + tid] * rsqrtf(var + 1e-5f);
            sA[tid] = A;
            sB[tid] = beta[(l - 1) * H + tid] - mu * A;
        } else { sA[tid] = 1.f; sB[tid] = 0.f; }
    }
    {   // linear fp16 weight copy
        const __half* wsrc = &g_WT[l * 6144];
        for (int i = tid; i < 1536; i += 256) {
            int e4 = i * 4;
            int cg = e4 >> 5;
            int h0 = e4 & 31;
            *reinterpret_cast<uint2*>(&sWT[cg * PIT + h0]) =
                *reinterpret_cast<const uint2*>(&wsrc[e4]);
        }
    }
    __syncthreads();

    // stage h as fp16 (apply BN affine; write back normalized g_h for l>0)
    int nb0 = blockIdx.x * 128;
    for (int i = tid; i < 128 * 8; i += 256) {
        int r = i >> 3, q4 = i & 7;
        int n = nb0 + r;
        float4 v = make_float4(0.f, 0.f, 0.f, 0.f);
        if (n < NN) {
            if (l == 0) v = *(const float4*)&g_h[n * H + q4 * 4];
            else {
                float4 hn = *(const float4*)&g_hnew[n * H + q4 * 4];
                float4 Av = *(const float4*)&sA[q4 * 4];
                float4 Bv = *(const float4*)&sB[q4 * 4];
                v.x = fmaf(hn.x, Av.x, Bv.x);
                v.y = fmaf(hn.y, Av.y, Bv.y);
                v.z = fmaf(hn.z, Av.z, Bv.z);
                v.w = fmaf(hn.w, Av.w, Bv.w);
                *(float4*)&g_h[n * H + q4 * 4] = v;
            }
        }
        __half2 p0 = __floats2half2_rn(v.x, v.y);
        __half2 p1 = __floats2half2_rn(v.z, v.w);
        uint2 pk;
        pk.x = *reinterpret_cast<u32*>(&p0);
        pk.y = *reinterpret_cast<u32*>(&p1);
        *reinterpret_cast<uint2*>(&sH[r * PIT + q4 * 4]) = pk;
    }
    __syncthreads();

    int wib = tid >> 5;
    int lane = tid & 31;
    int g = lane >> 2;
    int q = lane & 3;
    int nb = nb0 + wib * 16;
    bool act = (nb < NN);           // whole-warp flag (16 | NN)
    int r0 = wib * 16 + g;

    u32 a[2][4];
    if (act) {
#pragma unroll
        for (int kk = 0; kk < 2; kk++) {
            int cb = 2 * q + 16 * kk;
            a[kk][0] = *reinterpret_cast<const u32*>(&sH[(r0)     * PIT + cb]);
            a[kk][1] = *reinterpret_cast<const u32*>(&sH[(r0 + 8) * PIT + cb]);
            a[kk][2] = *reinterpret_cast<const u32*>(&sH[(r0)     * PIT + cb + 8]);
            a[kk][3] = *reinterpret_cast<const u32*>(&sH[(r0 + 8) * PIT + cb + 8]);
        }
    }
    __syncthreads();   // all fragments in regs before sH is reused as output buffer

    // Ph planes m=0..4: mma → smem (pitch 40, conflict-free) → coalesced uint4 stores
    for (int m = 0; m < 5; m++) {
        if (act) {
#pragma unroll
            for (int jt = 0; jt < 4; jt++) {
                const __half* wrow = &sWT[(m * 32 + jt * 8 + g) * PIT];
                u32 b0a = *reinterpret_cast<const u32*>(&wrow[2 * q]);
                u32 b1a = *reinterpret_cast<const u32*>(&wrow[2 * q + 8]);
                u32 b0b = *reinterpret_cast<const u32*>(&wrow[2 * q + 16]);
                u32 b1b = *reinterpret_cast<const u32*>(&wrow[2 * q + 24]);
                float c0 = 0.f, c1 = 0.f, c2 = 0.f, c3 = 0.f;
                mma16816(c0, c1, c2, c3, a[0][0], a[0][1], a[0][2], a[0][3], b0a, b1a);
                mma16816(c0, c1, c2, c3, a[1][0], a[1][1], a[1][2], a[1][3], b0b, b1b);
                int colb = jt * 8 + 2 * q;
                *reinterpret_cast<__half2*>(&sH[(wib * 16 + g)     * PIT + colb]) =
                    __floats2half2_rn(c0, c1);
                *reinterpret_cast<__half2*>(&sH[(wib * 16 + 8 + g) * PIT + colb]) =
                    __floats2half2_rn(c2, c3);
            }
        }
        __syncthreads();
        for (int i = tid; i < 512; i += 256) {      // 128 nodes × 4 × 16B chunks
            int n = i >> 2, c8 = i & 3;
            int gn = nb0 + n;
            if (gn < NN)
                *reinterpret_cast<uint4*>(&g_Ph[gn * 5 * H + m * H + c8 * 8]) =
                    *reinterpret_cast<const uint4*>(&sH[n * PIT + c8 * 8]);
        }
        __syncthreads();
    }

    // hr (m=5, fp32): direct stores
    if (act) {
        int n1 = nb + g;
        int n2 = n1 + 8;
#pragma unroll
        for (int jt = 0; jt < 4; jt++) {
            const __half* wrow = &sWT[(5 * 32 + jt * 8 + g) * PIT];
            u32 b0a = *reinterpret_cast<const u32*>(&wrow[2 * q]);
            u32 b1a = *reinterpret_cast<const u32*>(&wrow[2 * q + 8]);
            u32 b0b = *reinterpret_cast<const u32*>(&wrow[2 * q + 16]);
            u32 b1b = *reinterpret_cast<const u32*>(&wrow[2 * q + 24]);
            float c0 = 0.f, c1 = 0.f, c2 = 0.f, c3 = 0.f;
            mma16816(c0, c1, c2, c3, a[0][0], a[0][1], a[0][2], a[0][3], b0a, b1a);
            mma16816(c0, c1, c2, c3, a[1][0], a[1][1], a[1][2], a[1][3], b0b, b1b);
            int colb = jt * 8 + 2 * q;
            *reinterpret_cast<float2*>(&g_hr[n1 * H + colb]) = make_float2(c0, c1);
            *reinterpret_cast<float2*>(&g_hr[n2 * H + colb]) = make_float2(c2, c3);
        }
    }
}

// ---------------- edge pass (octet per edge, fp16 P gather, fp32 math, vector RED).
//                  Also resets global BN sums. ----------------
__global__ void k_edge(const int* __restrict__ ei, const float* __restrict__ et) {
    int gid = blockIdx.x * blockDim.x + threadIdx.x;
    if (gid < H)          g_bnsum[gid] = 0.f;
    else if (gid < 2 * H) g_bnsq[gid - H] = 0.f;
    int e = gid >> 3;
    int q = gid & 7;
    if (e >= EE) return;
    int s = ei[e];
    int t = ei[EE + e];
    float4 ev = *(const float4*)&et[e * ETT];
    const __half* __restrict__ Pr = &g_Ph[s * 5 * H];
    float4 p0 = ldP4h(&Pr[0 * H + q * 4]);
    float4 p1 = ldP4h(&Pr[1 * H + q * 4]);
    float4 p2 = ldP4h(&Pr[2 * H + q * 4]);
    float4 p3 = ldP4h(&Pr[3 * H + q * 4]);
    float4 p4 = ldP4h(&Pr[4 * H + q * 4]);
    float4 acc;
    acc.x = fmaf(ev.x, p0.x, fmaf(ev.y, p1.x, fmaf(ev.z, p2.x, fmaf(ev.w, p3.x, p4.x))));
    acc.y = fmaf(ev.x, p0.y, fmaf(ev.y, p1.y, fmaf(ev.z, p2.y, fmaf(ev.w, p3.y, p4.y))));
    acc.z = fmaf(ev.x, p0.z, fmaf(ev.y, p1.z, fmaf(ev.z, p2.z, fmaf(ev.w, p3.z, p4.z))));
    acc.w = fmaf(ev.x, p0.w, fmaf(ev.y, p1.w, fmaf(ev.z, p2.w, fmaf(ev.w, p3.w, p4.w))));
    redAddF4(&g_agg[t * H + q * 4], acc);
}

// ---------------- node update: warp walks 8 consecutive nodes (batch sorted →
//                  run-length pool accumulation); BN sums via global atomics ----------------
__global__ void k_update(const float* __restrict__ cb, const int* __restrict__ batch, int l) {
    __shared__ float ssum[H], ssq[H];
    int tid = threadIdx.x;
    int lane = tid & 31;
    int wib = tid >> 5;
    if (tid < H) { ssum[tid] = 0.f; ssq[tid] = 0.f; }
    __syncthreads();
    float bias = cb[l * H + lane];
    float lsum = 0.f, lsq = 0.f;
    float* psum = &g_poolsum[l * BB * H];
    float* pmax = &g_poolmax[l * BB * H];
    int base = (blockIdx.x * 8 + wib) * 8;
    if (base < NN) {
        int gcur = -1;
        float ps = 0.f, pm = 0.f;
#pragma unroll
        for (int j = 0; j < 8; j++) {
            int n = base + j;
            if (n >= NN) break;
            int i = n * H + lane;
            float hv = g_h[i];
            float nx = bias + g_agg[i] * g_invdeg[n] + g_hr[i];
            g_agg[i] = 0.f;
            int g = batch[n];
            float hp = fmaxf(nx, 0.f) + hv;
            g_hnew[i] = hp;
            lsum += hp; lsq += hp * hp;
            if (g != gcur) {
                if (gcur >= 0) {
                    atomicAdd(&psum[gcur * H + lane], ps);
                    atomicMaxFloat(&pmax[gcur * H + lane], pm);
                }
                gcur = g; ps = nx; pm = nx;
            } else {
                ps += nx; pm = fmaxf(pm, nx);
            }
        }
        if (gcur >= 0) {
            atomicAdd(&psum[gcur * H + lane], ps);
            atomicMaxFloat(&pmax[gcur * H + lane], pm);
        }
    }
    atomicAdd(&ssum[lane], lsum);
    atomicAdd(&ssq[lane], lsq);
    __syncthreads();
    if (tid < H) {
        atomicAdd(&g_bnsum[tid], ssum[tid]);
        atomicAdd(&g_bnsq[tid], ssq[tid]);
    }
}

// ---------------- final MLP: pool-finish fused into the feature load ----------------
__global__ void k_final(const float* __restrict__ w0, const float* __restrict__ b0,
                        const float* __restrict__ w1, const float* __restrict__ b1,
                        float* __restrict__ out) {
    __shared__ float sf[GPB * FEATP];
    __shared__ float st[GPB * HLD];
    int tid = threadIdx.x;
    int g0 = blockIdx.x * GPB;
    for (int i = tid; i < GPB * FEATP; i += blockDim.x) {
        int gg = i / FEATP, r = i - gg * FEATP;
        int g = g0 + gg;
        float v = 0.f;
        if (r < 53) {
            v = g_feats[g * FEAT + r];
        } else if (r < FEAT) {
            int rr = r - 53;
            int l = rr >> 6, k = rr & 63;
            float cnt = g_cnt[g];
            if (k < 32) v = g_poolsum[l * BB * H + g * H + k] / fmaxf(cnt, 1.f);
            else        v = (cnt > 0.f) ? g_poolmax[l * BB * H + g * H + (k - 32)] : 0.f;
        }
        sf[i] = v;
    }
    __syncthreads();
    {
        float acc[GPB];
        float bb = b0[tid];
#pragma unroll
        for (int gg = 0; gg < GPB; gg++) acc[gg] = bb;
        for (int i = 0; i < 244; i += 4) {
            float wa = w0[(i + 0) * HLD + tid];
            float wb = w0[(i + 1) * HLD + tid];
            float wc = w0[(i + 2) * HLD + tid];
            float wd = w0[(i + 3) * HLD + tid];
#pragma unroll
            for (int gg = 0; gg < GPB; gg++) {
                float4 f = *(const float4*)&sf[gg * FEATP + i];
                acc[gg] = fmaf(f.x, wa, acc[gg]);
                acc[gg] = fmaf(f.y, wb, acc[gg]);
                acc[gg] = fmaf(f.z, wc, acc[gg]);
                acc[gg] = fmaf(f.w, wd, acc[gg]);
            }
        }
        float wl = w0[244 * HLD + tid];
#pragma unroll
        for (int gg = 0; gg < GPB; gg++) acc[gg] = fmaf(sf[gg * FEATP + 244], wl, acc[gg]);
#pragma unroll
        for (int gg = 0; gg < GPB; gg++) st[gg * HLD + tid] = fmaxf(acc[gg], 0.f);
    }
    __syncthreads();
    {
        int col = tid & 127;
        int gbase = (tid >> 7) * 4;
        float bb = b1[col];
        float acc[4];
#pragma unroll
        for (int q = 0; q < 4; q++) acc[q] = bb;
        for (int i = 0; i < HLD; i += 4) {
            float wa = w1[(i + 0) * 2 * LAT + col];
            float wb = w1[(i + 1) * 2 * LAT + col];
            float wc = w1[(i + 2) * 2 * LAT + col];
            float wd = w1[(i + 3) * 2 * LAT + col];
#pragma unroll
            for (int q = 0; q < 4; q++) {
                float4 s4 = *(const float4*)&st[(gbase + q) * HLD + i];
                acc[q] = fmaf(s4.x, wa, acc[q]);
                acc[q] = fmaf(s4.y, wb, acc[q]);
                acc[q] = fmaf(s4.z, wc, acc[q]);
                acc[q] = fmaf(s4.w, wd, acc[q]);
            }
        }
#pragma unroll
        for (int q = 0; q < 4; q++) {
            int g = g0 + gbase + q;
            if (col < LAT) out[g * LAT + col] = acc[q];
            else           out[BB * LAT + g * LAT + (col - LAT)] = acc[q];
        }
    }
}

// ---------------- launch ----------------
extern "C" void kernel_launch(void* const* d_in, const int* in_sizes, int n_in,
                              void* d_out, int out_size) {
    const float* x      = (const float*)d_in[0];
    const int*   ei     = (const int*)  d_in[1];
    const float* et     = (const float*)d_in[2];
    const int*   batch  = (const int*)  d_in[3];
    const float* mlp0_w = (const float*)d_in[4];
    const float* mlp0_b = (const float*)d_in[5];
    const float* mlp1_w = (const float*)d_in[6];
    const float* mlp1_b = (const float*)d_in[7];
    const float* enw    = (const float*)d_in[8];
    const float* enb    = (const float*)d_in[9];
    const float* rw     = (const float*)d_in[10];
    const float* cb     = (const float*)d_in[11];
    const float* gamma  = (const float*)d_in[12];
    const float* beta   = (const float*)d_in[13];
    const float* f0w    = (const float*)d_in[14];
    const float* f0b    = (const float*)d_in[15];
    const float* f1w    = (const float*)d_in[16];
    const float* f1b    = (const float*)d_in[17];
    float* out = (float*)d_out;

    k_zero<<<(NN * H / 4 + 255) / 256, 256>>>();
    k_stats<<<(EE + 255) / 256, 256>>>(ei, et, x, batch, enw, enb, rw);
    k_init_mlp<<<(NN + 255) / 256, 256>>>(x, mlp0_w, mlp0_b, mlp1_w, mlp1_b);

    for (int l = 0; l < LL; l++) {
        k_precompute<<<(NN + 127) / 128, 256>>>(gamma, beta, l);
        k_edge<<<(EE * 8 + 255) / 256, 256>>>(ei, et);
        k_update<<<(NN + 63) / 64, 256>>>(cb, batch, l);
    }

    k_final<<<BB / GPB, 256>>>(f0w, f0b, f1w, f1b, out);
}

// round 16
// speedup vs baseline: 1.2624x; 1.1497x over previous
#include <cuda_runtime.h>
#include <cuda_fp16.h>
#include <math.h>

#define NN   50000
#define EE   200000
#define BB   2048
#define ATT  16
#define ETT  4
#define H    32
#define LL   3
#define LAT  64
#define HLD  256
#define FEAT 245
#define FEATP 248
#define MAXN 50.0f
#define GPB  16
#define PIT  40     // smem half pitch (conflict-free fragment loads; 80B rows, 16B-aligned)

typedef unsigned int u32;

// ---------------- scratch (device globals; no allocation allowed) ----------------
__device__ float  g_h[NN * H];           // current (normalized) node features
__device__ float  g_hnew[NN * H];        // pre-BN features (relu(nx)+h)
__device__ __half g_Ph[NN * 5 * H];      // fp16: per-node h@W_t (t=0..3) and h@Bmat (t=4)
__device__ float  g_hr[NN * H];          // per-node h@root_w (fp32)
__device__ float  g_agg[NN * H];
__device__ float  g_deg[NN];
__device__ float  g_invdeg[NN];
__device__ float  g_cnt[BB];
__device__ float  g_ec[BB * 4];          // 16B-aligned edge-type counts (vector RED target)
__device__ float  g_feats[BB * FEAT];    // only cols [0,53) used directly
__device__ float  g_poolsum[LL * BB * H];
__device__ float  g_poolmax[LL * BB * H];
__device__ float  g_bnsum[H];
__device__ float  g_bnsq[H];
__device__ __half g_WT[LL * 6 * H * H];  // pre-transposed fp16 weights [l][m][col][hh]

// float atomic max via monotone int/uint mapping
__device__ __forceinline__ void atomicMaxFloat(float* addr, float v) {
    if (v >= 0.f) atomicMax((int*)addr, __float_as_int(v));
    else          atomicMin((unsigned int*)addr, __float_as_uint(v));
}

// vector reduction: one instruction, 16B per lane
__device__ __forceinline__ void redAddF4(float* addr, float4 v) {
    asm volatile("red.global.add.v4.f32 [%0], {%1, %2, %3, %4};"
                 :: "l"(addr), "f"(v.x), "f"(v.y), "f"(v.z), "f"(v.w) : "memory");
}

// load 4 consecutive halves (8B) and widen to float4
__device__ __forceinline__ float4 ldP4h(const __half* p) {
    uint2 u = *(const uint2*)p;
    __half2 a = *reinterpret_cast<__half2*>(&u.x);
    __half2 b = *reinterpret_cast<__half2*>(&u.y);
    float2 fa = __half22float2(a), fb = __half22float2(b);
    return make_float4(fa.x, fa.y, fb.x, fb.y);
}

// mma.sync m16n8k16 fp16 in / fp32 accumulate
__device__ __forceinline__ void mma16816(float& c0, float& c1, float& c2, float& c3,
                                         u32 a0, u32 a1, u32 a2, u32 a3, u32 b0, u32 b1) {
    asm volatile(
        "mma.sync.aligned.m16n8k16.row.col.f32.f16.f16.f32 "
        "{%0,%1,%2,%3}, {%4,%5,%6,%7}, {%8,%9}, {%0,%1,%2,%3};"
        : "+f"(c0), "+f"(c1), "+f"(c2), "+f"(c3)
        : "r"(a0), "r"(a1), "r"(a2), "r"(a3), "r"(b0), "r"(b1));
}

// ---------------- one-time zero (float4) ----------------
__global__ void k_zero() {
    int i = blockIdx.x * blockDim.x + threadIdx.x;
    const float4 z4 = make_float4(0.f, 0.f, 0.f, 0.f);
    const float4 ninf4 = make_float4(-INFINITY, -INFINITY, -INFINITY, -INFINITY);
    if (i < NN * H / 4)      ((float4*)g_agg)[i] = z4;
    if (i < BB * FEAT / 4)   ((float4*)g_feats)[i] = z4;
    if (i < NN / 4)          ((float4*)g_deg)[i] = z4;
    if (i < BB / 4)          ((float4*)g_cnt)[i] = z4;
    if (i < BB)              ((float4*)g_ec)[i] = z4;
    if (i < LL * BB * H / 4) { ((float4*)g_poolsum)[i] = z4; ((float4*)g_poolmax)[i] = ninf4; }
    if (i < H)               { g_bnsum[i] = 0.f; g_bnsq[i] = 0.f; }
}

// ---------------- fused: edge stats (vector RED) + x pools (run-length) + weight pre-transform ----------------
__global__ void k_stats(const int* __restrict__ ei, const float* __restrict__ et,
                        const float* __restrict__ x, const int* __restrict__ batch,
                        const float* __restrict__ enw, const float* __restrict__ enb,
                        const float* __restrict__ rw) {
    int i = blockIdx.x * blockDim.x + threadIdx.x;
    if (i < LL * 6 * H * H) {
        int l = i / 6144, rd = i % 6144;
        int m = rd >> 10, rest = rd & 1023;
        int col = rest >> 5, hh = rest & 31;     // dest layout [m][col][hh]
        float w;
        if (m < 4)       w = enw[(l * ETT + m) * H * H + hh * H + col];
        else if (m == 4) w = enb[l * H * H + hh * H + col];
        else             w = rw[l * H * H + hh * H + col];
        g_WT[i] = __float2half(w);
    }
    if (i < (NN / 8) * 16) {
        int c = i & 15;
        int base = (i >> 4) * 8;
        int gcur = -1;
        float s = 0.f, mx = 0.f, cnt = 0.f;
#pragma unroll
        for (int j = 0; j < 8; j++) {
            int n = base + j;
            if (n >= NN) break;
            int g = batch[n];
            float v = x[n * ATT + c];
            if (g != gcur) {
                if (gcur >= 0) {
                    atomicAdd(&g_feats[gcur * FEAT + 21 + c], s);
                    atomicMaxFloat(&g_feats[gcur * FEAT + 37 + c], mx);
                    if (c == 0) atomicAdd(&g_cnt[gcur], cnt);
                }
                gcur = g; s = v; mx = v; cnt = 1.f;
            } else { s += v; mx = fmaxf(mx, v); cnt += 1.f; }
        }
        if (gcur >= 0) {
            atomicAdd(&g_feats[gcur * FEAT + 21 + c], s);
            atomicMaxFloat(&g_feats[gcur * FEAT + 37 + c], mx);
            if (c == 0) atomicAdd(&g_cnt[gcur], cnt);
        }
    }
    if (i < EE) {
        int s = ei[i];
        int t = ei[EE + i];
        atomicAdd(&g_deg[t], 1.f);
        int g = batch[s];
        const float inv = 1.f / MAXN;
        float4 ev = *(const float4*)&et[i * ETT];
        redAddF4(&g_ec[g * 4], make_float4(ev.x * inv, ev.y * inv, ev.z * inv, ev.w * inv));
    }
}

// ---------------- initial node MLP (thread per node) + invdeg / x-feature / ec finish ----------------
__global__ void k_init_mlp(const float* __restrict__ x,
                           const float* __restrict__ w0, const float* __restrict__ b0,
                           const float* __restrict__ w1, const float* __restrict__ b1) {
    __shared__ float sw0[ATT * H], sw1[H * H], sb0[H], sb1[H];
    int tid = threadIdx.x;
    for (int i = tid; i < ATT * H; i += blockDim.x) sw0[i] = w0[i];
    for (int i = tid; i < H * H;  i += blockDim.x) sw1[i] = w1[i];
    if (tid < H) { sb0[tid] = b0[tid]; sb1[tid] = b1[tid]; }
    __syncthreads();

    int gid = blockIdx.x * blockDim.x + tid;
    if (gid < NN) g_invdeg[gid] = 1.f / fmaxf(g_deg[gid], 1.f);
    if (gid < BB * 4) g_feats[(gid >> 2) * FEAT + 1 + (gid & 3)] = g_ec[gid];
    if (gid < BB * ATT) {
        int g = gid / ATT, c = gid % ATT;
        float cnt = g_cnt[g];
        float sum = g_feats[g * FEAT + 21 + c];
        g_feats[g * FEAT + 5 + c]  = sum / MAXN;
        g_feats[g * FEAT + 21 + c] = sum / fmaxf(cnt, 1.f);
        if (cnt <= 0.f) g_feats[g * FEAT + 37 + c] = 0.f;
        if (c == 0) g_feats[g * FEAT] = cnt / MAXN;
    }

    int n = gid;
    if (n >= NN) return;
    float xr[ATT];
#pragma unroll
    for (int q = 0; q < ATT / 4; q++) {
        float4 v = *(const float4*)&x[n * ATT + q * 4];
        xr[q * 4 + 0] = v.x; xr[q * 4 + 1] = v.y; xr[q * 4 + 2] = v.z; xr[q * 4 + 3] = v.w;
    }
    float t[H];
#pragma unroll
    for (int o = 0; o < H / 4; o++) {
        float4 bv = *(const float4*)&sb0[o * 4];
        t[o * 4 + 0] = bv.x; t[o * 4 + 1] = bv.y; t[o * 4 + 2] = bv.z; t[o * 4 + 3] = bv.w;
    }
#pragma unroll
    for (int a = 0; a < ATT; a++) {
        float xa = xr[a];
#pragma unroll
        for (int o = 0; o < H / 4; o++) {
            float4 w = *(const float4*)&sw0[a * H + o * 4];
            t[o * 4 + 0] = fmaf(xa, w.x, t[o * 4 + 0]);
            t[o * 4 + 1] = fmaf(xa, w.y, t[o * 4 + 1]);
            t[o * 4 + 2] = fmaf(xa, w.z, t[o * 4 + 2]);
            t[o * 4 + 3] = fmaf(xa, w.w, t[o * 4 + 3]);
        }
    }
    float hv[H];
#pragma unroll
    for (int o = 0; o < H / 4; o++) {
        float4 bv = *(const float4*)&sb1[o * 4];
        hv[o * 4 + 0] = bv.x; hv[o * 4 + 1] = bv.y; hv[o * 4 + 2] = bv.z; hv[o * 4 + 3] = bv.w;
    }
#pragma unroll
    for (int k = 0; k < H; k++) {
        float tk = fmaxf(t[k], 0.f);
#pragma unroll
        for (int o = 0; o < H / 4; o++) {
            float4 w = *(const float4*)&sw1[k * H + o * 4];
            hv[o * 4 + 0] = fmaf(tk, w.x, hv[o * 4 + 0]);
            hv[o * 4 + 1] = fmaf(tk, w.y, hv[o * 4 + 1]);
            hv[o * 4 + 2] = fmaf(tk, w.z, hv[o * 4 + 2]);
            hv[o * 4 + 3] = fmaf(tk, w.w, hv[o * 4 + 3]);
        }
    }
#pragma unroll
    for (int o = 0; o < H / 4; o++)
        *(float4*)&g_h[n * H + o * 4] = make_float4(hv[o*4], hv[o*4+1], hv[o*4+2], hv[o*4+3]);
}

// ---------------- precompute GEMM on tensor cores (256 thr / 128 nodes, grid 391).
//                  Ph stores staged through smem → coalesced uint4 stores.
//                  Fuses prev-layer BN-finish. ----------------
__global__ void k_precompute(const float* __restrict__ gamma, const float* __restrict__ beta,
                             int l) {
    __shared__ __half sWT[192 * PIT];   // 15 KB
    __shared__ __half sH[128 * PIT];    // 10 KB: h staging, then Ph epilogue buffer
    __shared__ float  sA[H], sB[H];
    int tid = threadIdx.x;

    if (tid < H) {
        if (l > 0) {
            float mu  = g_bnsum[tid] / (float)NN;
            float var = g_bnsq[tid] / (float)NN - mu * mu;
            float A = gamma[(l - 1) * H + tid] * rsqrtf(var + 1e-5f);
            sA[tid] = A;
            sB[tid] = beta[(l - 1) * H + tid] - mu * A;
        } else { sA[tid] = 1.f; sB[tid] = 0.f; }
    }
    {   // linear fp16 weight copy
        const __half* wsrc = &g_WT[l * 6144];
        for (int i = tid; i < 1536; i += 256) {
            int e4 = i * 4;
            int cg = e4 >> 5;
            int h0 = e4 & 31;
            *reinterpret_cast<uint2*>(&sWT[cg * PIT + h0]) =
                *reinterpret_cast<const uint2*>(&wsrc[e4]);
        }
    }
    __syncthreads();

    // stage h as fp16 (apply BN affine; write back normalized g_h for l>0)
    int nb0 = blockIdx.x * 128;
    for (int i = tid; i < 128 * 8; i += 256) {
        int r = i >> 3, q4 = i & 7;
        int n = nb0 + r;
        float4 v = make_float4(0.f, 0.f, 0.f, 0.f);
        if (n < NN) {
            if (l == 0) v = *(const float4*)&g_h[n * H + q4 * 4];
            else {
                float4 hn = *(const float4*)&g_hnew[n * H + q4 * 4];
                float4 Av = *(const float4*)&sA[q4 * 4];
                float4 Bv = *(const float4*)&sB[q4 * 4];
                v.x = fmaf(hn.x, Av.x, Bv.x);
                v.y = fmaf(hn.y, Av.y, Bv.y);
                v.z = fmaf(hn.z, Av.z, Bv.z);
                v.w = fmaf(hn.w, Av.w, Bv.w);
                *(float4*)&g_h[n * H + q4 * 4] = v;
            }
        }
        __half2 p0 = __floats2half2_rn(v.x, v.y);
        __half2 p1 = __floats2half2_rn(v.z, v.w);
        uint2 pk;
        pk.x = *reinterpret_cast<u32*>(&p0);
        pk.y = *reinterpret_cast<u32*>(&p1);
        *reinterpret_cast<uint2*>(&sH[r * PIT + q4 * 4]) = pk;
    }
    __syncthreads();

    int wib = tid >> 5;
    int lane = tid & 31;
    int g = lane >> 2;
    int q = lane & 3;
    int nb = nb0 + wib * 16;
    bool act = (nb < NN);           // whole-warp flag (16 | NN)
    int r0 = wib * 16 + g;

    u32 a[2][4];
    if (act) {
#pragma unroll
        for (int kk = 0; kk < 2; kk++) {
            int cb = 2 * q + 16 * kk;
            a[kk][0] = *reinterpret_cast<const u32*>(&sH[(r0)     * PIT + cb]);
            a[kk][1] = *reinterpret_cast<const u32*>(&sH[(r0 + 8) * PIT + cb]);
            a[kk][2] = *reinterpret_cast<const u32*>(&sH[(r0)     * PIT + cb + 8]);
            a[kk][3] = *reinterpret_cast<const u32*>(&sH[(r0 + 8) * PIT + cb + 8]);
        }
    }
    __syncthreads();   // all fragments in regs before sH is reused as output buffer

    // Ph planes m=0..4: mma → smem (pitch 40, conflict-free) → coalesced uint4 stores
    for (int m = 0; m < 5; m++) {
        if (act) {
#pragma unroll
            for (int jt = 0; jt < 4; jt++) {
                const __half* wrow = &sWT[(m * 32 + jt * 8 + g) * PIT];
                u32 b0a = *reinterpret_cast<const u32*>(&wrow[2 * q]);
                u32 b1a = *reinterpret_cast<const u32*>(&wrow[2 * q + 8]);
                u32 b0b = *reinterpret_cast<const u32*>(&wrow[2 * q + 16]);
                u32 b1b = *reinterpret_cast<const u32*>(&wrow[2 * q + 24]);
                float c0 = 0.f, c1 = 0.f, c2 = 0.f, c3 = 0.f;
                mma16816(c0, c1, c2, c3, a[0][0], a[0][1], a[0][2], a[0][3], b0a, b1a);
                mma16816(c0, c1, c2, c3, a[1][0], a[1][1], a[1][2], a[1][3], b0b, b1b);
                int colb = jt * 8 + 2 * q;
                *reinterpret_cast<__half2*>(&sH[(wib * 16 + g)     * PIT + colb]) =
                    __floats2half2_rn(c0, c1);
                *reinterpret_cast<__half2*>(&sH[(wib * 16 + 8 + g) * PIT + colb]) =
                    __floats2half2_rn(c2, c3);
            }
        }
        __syncthreads();
        for (int i = tid; i < 512; i += 256) {      // 128 nodes × 4 × 16B chunks
            int n = i >> 2, c8 = i & 3;
            int gn = nb0 + n;
            if (gn < NN)
                *reinterpret_cast<uint4*>(&g_Ph[gn * 5 * H + m * H + c8 * 8]) =
                    *reinterpret_cast<const uint4*>(&sH[n * PIT + c8 * 8]);
        }
        __syncthreads();
    }

    // hr (m=5, fp32): direct stores
    if (act) {
        int n1 = nb + g;
        int n2 = n1 + 8;
#pragma unroll
        for (int jt = 0; jt < 4; jt++) {
            const __half* wrow = &sWT[(5 * 32 + jt * 8 + g) * PIT];
            u32 b0a = *reinterpret_cast<const u32*>(&wrow[2 * q]);
            u32 b1a = *reinterpret_cast<const u32*>(&wrow[2 * q + 8]);
            u32 b0b = *reinterpret_cast<const u32*>(&wrow[2 * q + 16]);
            u32 b1b = *reinterpret_cast<const u32*>(&wrow[2 * q + 24]);
            float c0 = 0.f, c1 = 0.f, c2 = 0.f, c3 = 0.f;
            mma16816(c0, c1, c2, c3, a[0][0], a[0][1], a[0][2], a[0][3], b0a, b1a);
            mma16816(c0, c1, c2, c3, a[1][0], a[1][1], a[1][2], a[1][3], b0b, b1b);
            int colb = jt * 8 + 2 * q;
            *reinterpret_cast<float2*>(&g_hr[n1 * H + colb]) = make_float2(c0, c1);
            *reinterpret_cast<float2*>(&g_hr[n2 * H + colb]) = make_float2(c2, c3);
        }
    }
}

// ---------------- edge pass (octet per edge, fp16 P gather, fp32 math, vector RED).
//                  Also resets global BN sums. ----------------
__global__ void k_edge(const int* __restrict__ ei, const float* __restrict__ et) {
    int gid = blockIdx.x * blockDim.x + threadIdx.x;
    if (gid < H)          g_bnsum[gid] = 0.f;
    else if (gid < 2 * H) g_bnsq[gid - H] = 0.f;
    int e = gid >> 3;
    int q = gid & 7;
    if (e >= EE) return;
    int s = ei[e];
    int t = ei[EE + e];
    float4 ev = *(const float4*)&et[e * ETT];
    const __half* __restrict__ Pr = &g_Ph[s * 5 * H];
    float4 p0 = ldP4h(&Pr[0 * H + q * 4]);
    float4 p1 = ldP4h(&Pr[1 * H + q * 4]);
    float4 p2 = ldP4h(&Pr[2 * H + q * 4]);
    float4 p3 = ldP4h(&Pr[3 * H + q * 4]);
    float4 p4 = ldP4h(&Pr[4 * H + q * 4]);
    float4 acc;
    acc.x = fmaf(ev.x, p0.x, fmaf(ev.y, p1.x, fmaf(ev.z, p2.x, fmaf(ev.w, p3.x, p4.x))));
    acc.y = fmaf(ev.x, p0.y, fmaf(ev.y, p1.y, fmaf(ev.z, p2.y, fmaf(ev.w, p3.y, p4.y))));
    acc.z = fmaf(ev.x, p0.z, fmaf(ev.y, p1.z, fmaf(ev.z, p2.z, fmaf(ev.w, p3.z, p4.z))));
    acc.w = fmaf(ev.x, p0.w, fmaf(ev.y, p1.w, fmaf(ev.z, p2.w, fmaf(ev.w, p3.w, p4.w))));
    redAddF4(&g_agg[t * H + q * 4], acc);
}

// ---------------- node update: warp walks 8 consecutive nodes (run-length pools).
//                  Last layer skips hnew/h/BN/agg-zero work (nothing downstream reads them). ----------------
__global__ void k_update(const float* __restrict__ cb, const int* __restrict__ batch, int l) {
    __shared__ float ssum[H], ssq[H];
    int tid = threadIdx.x;
    int lane = tid & 31;
    int wib = tid >> 5;
    bool last = (l == LL - 1);
    if (tid < H) { ssum[tid] = 0.f; ssq[tid] = 0.f; }
    __syncthreads();
    float bias = cb[l * H + lane];
    float lsum = 0.f, lsq = 0.f;
    float* psum = &g_poolsum[l * BB * H];
    float* pmax = &g_poolmax[l * BB * H];
    int base = (blockIdx.x * 8 + wib) * 8;
    if (base < NN) {
        int gcur = -1;
        float ps = 0.f, pm = 0.f;
#pragma unroll
        for (int j = 0; j < 8; j++) {
            int n = base + j;
            if (n >= NN) break;
            int i = n * H + lane;
            float nx = bias + g_agg[i] * g_invdeg[n] + g_hr[i];
            int g = batch[n];
            if (!last) {
                float hv = g_h[i];
                g_agg[i] = 0.f;
                float hp = fmaxf(nx, 0.f) + hv;
                g_hnew[i] = hp;
                lsum += hp; lsq += hp * hp;
            }
            if (g != gcur) {
                if (gcur >= 0) {
                    atomicAdd(&psum[gcur * H + lane], ps);
                    atomicMaxFloat(&pmax[gcur * H + lane], pm);
                }
                gcur = g; ps = nx; pm = nx;
            } else {
                ps += nx; pm = fmaxf(pm, nx);
            }
        }
        if (gcur >= 0) {
            atomicAdd(&psum[gcur * H + lane], ps);
            atomicMaxFloat(&pmax[gcur * H + lane], pm);
        }
    }
    if (!last) {
        atomicAdd(&ssum[lane], lsum);
        atomicAdd(&ssq[lane], lsq);
        __syncthreads();
        if (tid < H) {
            atomicAdd(&g_bnsum[tid], ssum[tid]);
            atomicAdd(&g_bnsq[tid], ssq[tid]);
        }
    }
}

// ---------------- final MLP: pool-finish fused into the feature load (16 graphs/block) ----------------
__global__ void k_final(const float* __restrict__ w0, const float* __restrict__ b0,
                        const float* __restrict__ w1, const float* __restrict__ b1,
                        float* __restrict__ out) {
    __shared__ float sf[GPB * FEATP];
    __shared__ float st[GPB * HLD];
    int tid = threadIdx.x;
    int g0 = blockIdx.x * GPB;
    for (int i = tid; i < GPB * FEATP; i += blockDim.x) {
        int gg = i / FEATP, r = i - gg * FEATP;
        int g = g0 + gg;
        float v = 0.f;
        if (r < 53) {
            v = g_feats[g * FEAT + r];
        } else if (r < FEAT) {
            int rr = r - 53;
            int l = rr >> 6, k = rr & 63;
            float cnt = g_cnt[g];
            if (k < 32) v = g_poolsum[l * BB * H + g * H + k] / fmaxf(cnt, 1.f);
            else        v = (cnt > 0.f) ? g_poolmax[l * BB * H + g * H + (k - 32)] : 0.f;
        }
        sf[i] = v;
    }
    __syncthreads();
    {
        float acc[GPB];
        float bb = b0[tid];
#pragma unroll
        for (int gg = 0; gg < GPB; gg++) acc[gg] = bb;
        for (int i = 0; i < 244; i += 4) {
            float wa = w0[(i + 0) * HLD + tid];
            float wb = w0[(i + 1) * HLD + tid];
            float wc = w0[(i + 2) * HLD + tid];
            float wd = w0[(i + 3) * HLD + tid];
#pragma unroll
            for (int gg = 0; gg < GPB; gg++) {
                float4 f = *(const float4*)&sf[gg * FEATP + i];
                acc[gg] = fmaf(f.x, wa, acc[gg]);
                acc[gg] = fmaf(f.y, wb, acc[gg]);
                acc[gg] = fmaf(f.z, wc, acc[gg]);
                acc[gg] = fmaf(f.w, wd, acc[gg]);
            }
        }
        float wl = w0[244 * HLD + tid];
#pragma unroll
        for (int gg = 0; gg < GPB; gg++) acc[gg] = fmaf(sf[gg * FEATP + 244], wl, acc[gg]);
#pragma unroll
        for (int gg = 0; gg < GPB; gg++) st[gg * HLD + tid] = fmaxf(acc[gg], 0.f);
    }
    __syncthreads();
    {
        int col = tid & 127;
        int gbase = (tid >> 7) * 8;
        float bb = b1[col];
        float acc[8];
#pragma unroll
        for (int q = 0; q < 8; q++) acc[q] = bb;
        for (int i = 0; i < HLD; i += 4) {
            float wa = w1[(i + 0) * 2 * LAT + col];
            float wb = w1[(i + 1) * 2 * LAT + col];
            float wc = w1[(i + 2) * 2 * LAT + col];
            float wd = w1[(i + 3) * 2 * LAT + col];
#pragma unroll
            for (int q = 0; q < 8; q++) {
                float4 s4 = *(const float4*)&st[(gbase + q) * HLD + i];
                acc[q] = fmaf(s4.x, wa, acc[q]);
                acc[q] = fmaf(s4.y, wb, acc[q]);
                acc[q] = fmaf(s4.z, wc, acc[q]);
                acc[q] = fmaf(s4.w, wd, acc[q]);
            }
        }
#pragma unroll
        for (int q = 0; q < 8; q++) {
            int g = g0 + gbase + q;
            if (col < LAT) out[g * LAT + col] = acc[q];
            else           out[BB * LAT + g * LAT + (col - LAT)] = acc[q];
        }
    }
}

// ---------------- launch ----------------
extern "C" void kernel_launch(void* const* d_in, const int* in_sizes, int n_in,
                              void* d_out, int out_size) {
    const float* x      = (const float*)d_in[0];
    const int*   ei     = (const int*)  d_in[1];
    const float* et     = (const float*)d_in[2];
    const int*   batch  = (const int*)  d_in[3];
    const float* mlp0_w = (const float*)d_in[4];
    const float* mlp0_b = (const float*)d_in[5];
    const float* mlp1_w = (const float*)d_in[6];
    const float* mlp1_b = (const float*)d_in[7];
    const float* enw    = (const float*)d_in[8];
    const float* enb    = (const float*)d_in[9];
    const float* rw     = (const float*)d_in[10];
    const float* cb     = (const float*)d_in[11];
    const float* gamma  = (const float*)d_in[12];
    const float* beta   = (const float*)d_in[13];
    const float* f0w    = (const float*)d_in[14];
    const float* f0b    = (const float*)d_in[15];
    const float* f1w    = (const float*)d_in[16];
    const float* f1b    = (const float*)d_in[17];
    float* out = (float*)d_out;

    k_zero<<<(NN * H / 4 + 255) / 256, 256>>>();
    k_stats<<<(EE + 255) / 256, 256>>>(ei, et, x, batch, enw, enb, rw);
    k_init_mlp<<<(NN + 255) / 256, 256>>>(x, mlp0_w, mlp0_b, mlp1_w, mlp1_b);

    for (int l = 0; l < LL; l++) {
        k_precompute<<<(NN + 127) / 128, 256>>>(gamma, beta, l);
        k_edge<<<(EE * 8 + 255) / 256, 256>>>(ei, et);
        k_update<<<(NN + 63) / 64, 256>>>(cb, batch, l);
    }

    k_final<<<BB / GPB, 256>>>(f0w, f0b, f1w, f1b, out);
}